// round 4
// baseline (speedup 1.0000x reference)
#include <cuda_runtime.h>
#include <cuda_bf16.h>

// Problem constants: B=32, C=3, H=W=512
#define Bv 32
#define Cv 3
#define Hv 512
#define Wv 512
#define PLANE (Hv*Wv)            // 262144
#define NPLANES (Bv*Cv)          // 96
#define K1_BLOCKS_PER_PLANE 32
#define RSTRIP 16                // output rows per K2 block

// Deterministic partial sums (no atomics): one slot per (plane, block)
__device__ float d_partial[NPLANES * K1_BLOCKS_PER_PLANE];

__device__ __forceinline__ float fast_pow(float x, float g) {
    return __powf(x, g);         // MUFU.LG2 + FMUL + MUFU.EX2 ; 0^g -> 0 correct
}

// ---------------- Kernel 1: per-plane sum of x^gamma ----------------
__global__ void __launch_bounds__(256) k1_pow_sum(const float* __restrict__ x,
                                                 const float* __restrict__ gamma) {
    const int plane = blockIdx.y;            // b*3 + c
    const int b = plane / Cv;
    const float g = __ldg(&gamma[b]);
    const float4* px = (const float4*)(x + (size_t)plane * PLANE);

    float s0 = 0.f, s1 = 0.f, s2 = 0.f, s3 = 0.f;
    int base = blockIdx.x * 2048 + threadIdx.x;   // 2048 float4 per block
#pragma unroll
    for (int k = 0; k < 8; k++) {
        float4 v = px[base + k * 256];
        s0 += fast_pow(v.x, g);
        s1 += fast_pow(v.y, g);
        s2 += fast_pow(v.z, g);
        s3 += fast_pow(v.w, g);
    }
    float s = (s0 + s1) + (s2 + s3);
#pragma unroll
    for (int o = 16; o; o >>= 1) s += __shfl_xor_sync(0xFFFFFFFFu, s, o);

    __shared__ float ws[8];
    int lane = threadIdx.x & 31, w = threadIdx.x >> 5;
    if (lane == 0) ws[w] = s;
    __syncthreads();
    if (w == 0) {
        s = (lane < 8) ? ws[lane] : 0.f;
#pragma unroll
        for (int o = 4; o; o >>= 1) s += __shfl_xor_sync(0xFFFFFFFFu, s, o);
        if (lane == 0) d_partial[plane * K1_BLOCKS_PER_PLANE + blockIdx.x] = s;
    }
}

// ---------------- Kernel 2: rolling register pipeline, no smem tile ----------------
// Block: 128 threads; thread t owns output columns 4t..4t+3 of a full 512-wide row.
// Iterates RSTRIP+2 input rows (1 halo above/below) with 1-row prefetch.
// Horizontal halo via warp shuffles + 2 predicated scalar LDG at warp edges.
__global__ void __launch_bounds__(128) k2_main(const float* __restrict__ x,
                                               const float* __restrict__ gamma,
                                               const float* __restrict__ wb,
                                               const float* __restrict__ contrast,
                                               const float* __restrict__ sharpen,
                                               float* __restrict__ out) {
    const int plane = blockIdx.y;            // b*3 + c
    const int b = plane / Cv;
    const float g  = __ldg(&gamma[b]);
    const float w  = __ldg(&wb[plane]);      // wb[b][c] flattens to wb[plane]
    const float ct = __ldg(&contrast[b]);
    const float s  = __ldg(&sharpen[b]);

    __shared__ float s_beta;
    const int tid  = threadIdx.x;
    const int lane = tid & 31;

    // Fold per-plane partials: warp 0, one load + shfl reduce.
    if (tid < 32) {
        float p = d_partial[plane * K1_BLOCKS_PER_PLANE + tid];
#pragma unroll
        for (int o = 16; o; o >>= 1) p += __shfl_xor_sync(0xFFFFFFFFu, p, o);
        if (tid == 0) {
            float mean = p * w * (1.0f / (float)PLANE);
            s_beta = mean - mean * ct;       // mean*(1-contrast)
        }
    }
    __syncthreads();
    const float beta = s_beta;

    const float* __restrict__ px = x + (size_t)plane * PLANE;
    float* __restrict__ po = out + (size_t)plane * PLANE;
    const int y0 = blockIdx.x * RSTRIP;
    const int cbase = (tid >> 5) * 128;      // warp's first column
    const bool evL = (lane == 0)  && (cbase > 0);
    const bool evR = (lane == 31) && (cbase + 128 < Wv);

    float rs0[4] = {0.f, 0.f, 0.f, 0.f};
    float rs1[4] = {0.f, 0.f, 0.f, 0.f};
    float ctr[4] = {0.f, 0.f, 0.f, 0.f};

    // Prologue: prefetch row y0-1
    float4 vn = make_float4(0.f, 0.f, 0.f, 0.f);
    float en = 0.f;
    {
        int gy = y0 - 1;
        if (gy >= 0) {
            vn = ((const float4*)(px + gy * Wv))[tid];
            if (evL) en = px[gy * Wv + cbase - 1];
            if (evR) en = px[gy * Wv + cbase + 128];
        }
    }

#pragma unroll 2
    for (int i = 0; i < RSTRIP + 2; i++) {
        const int gy = y0 - 1 + i;
        const bool vval = (gy >= 0) && (gy < Hv);
        float4 v = vn;
        float eraw = en;

        // Prefetch next row
        vn = make_float4(0.f, 0.f, 0.f, 0.f);
        en = 0.f;
        const int gyn = gy + 1;
        if (i < RSTRIP + 1 && gyn < Hv) {
            vn = ((const float4*)(px + gyn * Wv))[tid];
            if (evL) en = px[gyn * Wv + cbase - 1];
            if (evR) en = px[gyn * Wv + cbase + 128];
        }

        // Transform current row (pow -> wb -> contrast -> clip)
        float f0 = fminf(fmaxf(fmaf(fast_pow(v.x, g) * w, ct, beta), 0.f), 1.f);
        float f1 = fminf(fmaxf(fmaf(fast_pow(v.y, g) * w, ct, beta), 0.f), 1.f);
        float f2 = fminf(fmaxf(fmaf(fast_pow(v.z, g) * w, ct, beta), 0.f), 1.f);
        float f3 = fminf(fmaxf(fmaf(fast_pow(v.w, g) * w, ct, beta), 0.f), 1.f);
        float e  = fminf(fmaxf(fmaf(fast_pow(eraw, g) * w, ct, beta), 0.f), 1.f);
        if (!vval) { f0 = f1 = f2 = f3 = 0.f; }
        if (!(vval && (evL || evR))) e = 0.f;

        // Horizontal neighbors via shuffle (warp edges use e)
        float fl = __shfl_up_sync(0xFFFFFFFFu, f3, 1);
        if (lane == 0) fl = e;
        float fr = __shfl_down_sync(0xFFFFFFFFu, f0, 1);
        if (lane == 31) fr = e;

        float rs2_0 = fl + f0 + f1;
        float rs2_1 = f0 + f1 + f2;
        float rs2_2 = f1 + f2 + f3;
        float rs2_3 = f2 + f3 + fr;

        // Emit output row gy-1 (uses rowsums gy-2, gy-1, gy and centers of gy-1)
        if (i >= 2) {
            float4 o4;
            float s9, c, sharp, val;

            c = ctr[0]; s9 = rs0[0] + rs1[0] + rs2_0;
            sharp = fmaf(10.f, c, -s9);
            val = fmaf(s, sharp - c, c);
            o4.x = fminf(fmaxf(val, 0.f), 1.f);

            c = ctr[1]; s9 = rs0[1] + rs1[1] + rs2_1;
            sharp = fmaf(10.f, c, -s9);
            val = fmaf(s, sharp - c, c);
            o4.y = fminf(fmaxf(val, 0.f), 1.f);

            c = ctr[2]; s9 = rs0[2] + rs1[2] + rs2_2;
            sharp = fmaf(10.f, c, -s9);
            val = fmaf(s, sharp - c, c);
            o4.z = fminf(fmaxf(val, 0.f), 1.f);

            c = ctr[3]; s9 = rs0[3] + rs1[3] + rs2_3;
            sharp = fmaf(10.f, c, -s9);
            val = fmaf(s, sharp - c, c);
            o4.w = fminf(fmaxf(val, 0.f), 1.f);

            ((float4*)(po + (gy - 1) * Wv))[tid] = o4;
        }

        // Rotate pipeline registers
        rs0[0] = rs1[0]; rs0[1] = rs1[1]; rs0[2] = rs1[2]; rs0[3] = rs1[3];
        rs1[0] = rs2_0;  rs1[1] = rs2_1;  rs1[2] = rs2_2;  rs1[3] = rs2_3;
        ctr[0] = f0; ctr[1] = f1; ctr[2] = f2; ctr[3] = f3;
    }
}

extern "C" void kernel_launch(void* const* d_in, const int* in_sizes, int n_in,
                              void* d_out, int out_size) {
    const float* x        = (const float*)d_in[0];
    const float* gamma    = (const float*)d_in[1];
    const float* wb       = (const float*)d_in[2];
    const float* contrast = (const float*)d_in[3];
    const float* sharpen  = (const float*)d_in[4];
    float* out = (float*)d_out;

    dim3 g1(K1_BLOCKS_PER_PLANE, NPLANES);
    k1_pow_sum<<<g1, 256>>>(x, gamma);
    dim3 g2(Hv / RSTRIP, NPLANES);           // 32 strips x 96 planes = 3072 blocks
    k2_main<<<g2, 128>>>(x, gamma, wb, contrast, sharpen, out);
}

// round 5
// speedup vs baseline: 1.0979x; 1.0979x over previous
#include <cuda_runtime.h>
#include <cuda_bf16.h>

// Problem constants: B=32, C=3, H=W=512
#define Bv 32
#define Cv 3
#define Hv 512
#define Wv 512
#define PLANE (Hv*Wv)            // 262144
#define NPLANES (Bv*Cv)          // 96
#define K1_BLOCKS_PER_PLANE 32
#define RSTRIP 16                // output rows per K2 block

// Deterministic partial sums (no atomics): one slot per (plane, block)
__device__ float d_partial[NPLANES * K1_BLOCKS_PER_PLANE];

__device__ __forceinline__ float fast_pow(float x, float g) {
    return __powf(x, g);         // MUFU.LG2 + FMUL + MUFU.EX2 ; 0^g -> 0 correct
}

// ---------------- Kernel 1: per-plane sum of x^gamma ----------------
__global__ void __launch_bounds__(256) k1_pow_sum(const float* __restrict__ x,
                                                 const float* __restrict__ gamma) {
    const int plane = blockIdx.y;            // b*3 + c
    const int b = plane / Cv;
    const float g = __ldg(&gamma[b]);
    const float4* px = (const float4*)(x + (size_t)plane * PLANE);

    float s0 = 0.f, s1 = 0.f, s2 = 0.f, s3 = 0.f;
    int base = blockIdx.x * 2048 + threadIdx.x;   // 2048 float4 per block
#pragma unroll
    for (int k = 0; k < 8; k++) {
        float4 v = px[base + k * 256];
        s0 += fast_pow(v.x, g);
        s1 += fast_pow(v.y, g);
        s2 += fast_pow(v.z, g);
        s3 += fast_pow(v.w, g);
    }
    float s = (s0 + s1) + (s2 + s3);
#pragma unroll
    for (int o = 16; o; o >>= 1) s += __shfl_xor_sync(0xFFFFFFFFu, s, o);

    __shared__ float ws[8];
    int lane = threadIdx.x & 31, w = threadIdx.x >> 5;
    if (lane == 0) ws[w] = s;
    __syncthreads();
    if (w == 0) {
        s = (lane < 8) ? ws[lane] : 0.f;
#pragma unroll
        for (int o = 4; o; o >>= 1) s += __shfl_xor_sync(0xFFFFFFFFu, s, o);
        if (lane == 0) d_partial[plane * K1_BLOCKS_PER_PLANE + blockIdx.x] = s;
    }
}

// ---------------- Kernel 2: rolling register pipeline, no smem tile ----------------
// Block: 128 threads; thread t owns output columns 4t..4t+3 of a full 512-wide row.
// Fully-unrolled RSTRIP+2 row walk with 1-row prefetch; horizontal halo via
// shuffles + 2 predicated scalar LDG at warp edges. All clips ride on FFMA.SAT.
__global__ void __launch_bounds__(128) k2_main(const float* __restrict__ x,
                                               const float* __restrict__ gamma,
                                               const float* __restrict__ wb,
                                               const float* __restrict__ contrast,
                                               const float* __restrict__ sharpen,
                                               float* __restrict__ out) {
    const int plane = blockIdx.y;            // b*3 + c
    const int b = plane / Cv;
    const float g  = __ldg(&gamma[b]);
    const float w  = __ldg(&wb[plane]);      // wb[b][c] flattens to wb[plane]
    const float ct = __ldg(&contrast[b]);
    const float s  = __ldg(&sharpen[b]);
    const float wct = w * ct;                // fold wb into contrast scale

    __shared__ float s_beta;
    const int tid  = threadIdx.x;
    const int lane = tid & 31;

    // Fold per-plane partials: warp 0, one load + shfl reduce.
    if (tid < 32) {
        float p = d_partial[plane * K1_BLOCKS_PER_PLANE + tid];
#pragma unroll
        for (int o = 16; o; o >>= 1) p += __shfl_xor_sync(0xFFFFFFFFu, p, o);
        if (tid == 0) {
            float mean = p * w * (1.0f / (float)PLANE);
            s_beta = mean - mean * ct;       // mean*(1-contrast)
        }
    }
    __syncthreads();
    const float beta = s_beta;

    const float* __restrict__ px = x + (size_t)plane * PLANE;
    float* __restrict__ po = out + (size_t)plane * PLANE;
    const int y0 = blockIdx.x * RSTRIP;
    const int cbase = (tid >> 5) * 128;      // warp's first column
    const bool evL = (lane == 0)  && (cbase > 0);
    const bool evR = (lane == 31) && (cbase + 128 < Wv);
    const int eoff = evL ? (cbase - 1) : (cbase + 128);   // edge column (if any)
    const bool ev  = evL || evR;

    float rs0[4] = {0.f, 0.f, 0.f, 0.f};
    float rs1[4] = {0.f, 0.f, 0.f, 0.f};
    float ctr[4] = {0.f, 0.f, 0.f, 0.f};

    // Prologue: prefetch row y0-1
    float4 vn = make_float4(0.f, 0.f, 0.f, 0.f);
    float en = 0.f;
    {
        int gy = y0 - 1;
        if (gy >= 0) {
            vn = ((const float4*)(px + gy * Wv))[tid];
            if (ev) en = px[gy * Wv + eoff];
        }
    }

#pragma unroll
    for (int i = 0; i < RSTRIP + 2; i++) {
        const int gy = y0 - 1 + i;
        const bool vval = (gy >= 0) && (gy < Hv);
        float4 v = vn;
        float eraw = en;

        // Prefetch next row
        vn = make_float4(0.f, 0.f, 0.f, 0.f);
        en = 0.f;
        const int gyn = gy + 1;
        if (i < RSTRIP + 1 && gyn < Hv) {
            vn = ((const float4*)(px + gyn * Wv))[tid];
            if (ev) en = px[gyn * Wv + eoff];
        }

        // Transform: sat(x^g * (w*ct) + beta)  -> FFMA.SAT
        float f0 = __saturatef(fmaf(fast_pow(v.x, g), wct, beta));
        float f1 = __saturatef(fmaf(fast_pow(v.y, g), wct, beta));
        float f2 = __saturatef(fmaf(fast_pow(v.z, g), wct, beta));
        float f3 = __saturatef(fmaf(fast_pow(v.w, g), wct, beta));
        float e  = __saturatef(fmaf(fast_pow(eraw, g), wct, beta));
        if (!vval) { f0 = f1 = f2 = f3 = 0.f; }
        if (!(vval && ev)) e = 0.f;

        // Horizontal neighbors via shuffle (warp edges use e)
        float fl = __shfl_up_sync(0xFFFFFFFFu, f3, 1);
        if (lane == 0) fl = e;
        float fr = __shfl_down_sync(0xFFFFFFFFu, f0, 1);
        if (lane == 31) fr = e;

        float rs2_0 = fl + f0 + f1;
        float rs2_1 = f0 + f1 + f2;
        float rs2_2 = f1 + f2 + f3;
        float rs2_3 = f2 + f3 + fr;

        // Emit output row gy-1: out = sat(s*(9c - s9) + c) -> FFMA + FFMA.SAT
        if (i >= 2) {
            float4 o4;
            float s9, c;

            c = ctr[0]; s9 = rs0[0] + rs1[0] + rs2_0;
            o4.x = __saturatef(fmaf(s, fmaf(9.f, c, -s9), c));

            c = ctr[1]; s9 = rs0[1] + rs1[1] + rs2_1;
            o4.y = __saturatef(fmaf(s, fmaf(9.f, c, -s9), c));

            c = ctr[2]; s9 = rs0[2] + rs1[2] + rs2_2;
            o4.z = __saturatef(fmaf(s, fmaf(9.f, c, -s9), c));

            c = ctr[3]; s9 = rs0[3] + rs1[3] + rs2_3;
            o4.w = __saturatef(fmaf(s, fmaf(9.f, c, -s9), c));

            ((float4*)(po + (gy - 1) * Wv))[tid] = o4;
        }

        // Rotate pipeline registers (renamed away by the full unroll)
        rs0[0] = rs1[0]; rs0[1] = rs1[1]; rs0[2] = rs1[2]; rs0[3] = rs1[3];
        rs1[0] = rs2_0;  rs1[1] = rs2_1;  rs1[2] = rs2_2;  rs1[3] = rs2_3;
        ctr[0] = f0; ctr[1] = f1; ctr[2] = f2; ctr[3] = f3;
    }
}

extern "C" void kernel_launch(void* const* d_in, const int* in_sizes, int n_in,
                              void* d_out, int out_size) {
    const float* x        = (const float*)d_in[0];
    const float* gamma    = (const float*)d_in[1];
    const float* wb       = (const float*)d_in[2];
    const float* contrast = (const float*)d_in[3];
    const float* sharpen  = (const float*)d_in[4];
    float* out = (float*)d_out;

    dim3 g1(K1_BLOCKS_PER_PLANE, NPLANES);
    k1_pow_sum<<<g1, 256>>>(x, gamma);
    dim3 g2(Hv / RSTRIP, NPLANES);           // 32 strips x 96 planes = 3072 blocks
    k2_main<<<g2, 128>>>(x, gamma, wb, contrast, sharpen, out);
}

// round 6
// speedup vs baseline: 1.1115x; 1.0124x over previous
#include <cuda_runtime.h>
#include <cuda_bf16.h>

// Problem constants: B=32, C=3, H=W=512
#define Bv 32
#define Cv 3
#define Hv 512
#define Wv 512
#define PLANE (Hv*Wv)            // 262144
#define NPLANES (Bv*Cv)          // 96
#define K1_BLOCKS_PER_PLANE 32
#define RSTRIP 16                // output rows per K2 block

// Deterministic partial sums (no atomics): one slot per (plane, block)
__device__ float d_partial[NPLANES * K1_BLOCKS_PER_PLANE];

__device__ __forceinline__ float fast_pow(float x, float g) {
    return __powf(x, g);         // MUFU.LG2 + FMUL + MUFU.EX2 ; 0^g -> 0 correct
}

// ---------------- Kernel 1: per-plane sum of x^gamma ----------------
__global__ void __launch_bounds__(256) k1_pow_sum(const float* __restrict__ x,
                                                 const float* __restrict__ gamma) {
    const int plane = blockIdx.y;            // b*3 + c
    const int b = plane / Cv;
    const float g = __ldg(&gamma[b]);
    const float4* px = (const float4*)(x + (size_t)plane * PLANE);

    float s0 = 0.f, s1 = 0.f, s2 = 0.f, s3 = 0.f;
    int base = blockIdx.x * 2048 + threadIdx.x;   // 2048 float4 per block
#pragma unroll
    for (int k = 0; k < 8; k++) {
        float4 v = px[base + k * 256];
        s0 += fast_pow(v.x, g);
        s1 += fast_pow(v.y, g);
        s2 += fast_pow(v.z, g);
        s3 += fast_pow(v.w, g);
    }
    float s = (s0 + s1) + (s2 + s3);
#pragma unroll
    for (int o = 16; o; o >>= 1) s += __shfl_xor_sync(0xFFFFFFFFu, s, o);

    __shared__ float ws[8];
    int lane = threadIdx.x & 31, w = threadIdx.x >> 5;
    if (lane == 0) ws[w] = s;
    __syncthreads();
    if (w == 0) {
        s = (lane < 8) ? ws[lane] : 0.f;
#pragma unroll
        for (int o = 4; o; o >>= 1) s += __shfl_xor_sync(0xFFFFFFFFu, s, o);
        if (lane == 0) d_partial[plane * K1_BLOCKS_PER_PLANE + blockIdx.x] = s;
    }
}

// ---------------- Kernel 2 body: rolling register pipeline ----------------
// Thread t owns output columns 4t..4t+3 of a full 512-wide row. Walks
// RSTRIP+2 input rows with DEPTH-2 prefetch; horizontal halo via shuffles +
// 2 predicated scalar LDG at warp edges. INTERIOR strips skip all vertical
// bounds checks (unconditional loads -> high MLP).
template <bool INTERIOR>
__device__ __forceinline__ void k2_body(const float* __restrict__ px,
                                        float* __restrict__ po,
                                        int y0, int tid, int lane,
                                        float g, float wct, float beta, float s) {
    const int cbase = (tid >> 5) * 128;      // warp's first column
    const bool evL = (lane == 0)  && (cbase > 0);
    const bool evR = (lane == 31) && (cbase + 128 < Wv);
    const int eoff = evL ? (cbase - 1) : (cbase + 128);
    const bool ev  = evL || evR;

    float rs0[4] = {0.f, 0.f, 0.f, 0.f};
    float rs1[4] = {0.f, 0.f, 0.f, 0.f};
    float ctr[4] = {0.f, 0.f, 0.f, 0.f};

    float4 vbuf[2];
    float  ebuf[2];

    // Prologue: prefetch rows y0-1 and y0
#pragma unroll
    for (int k = 0; k < 2; k++) {
        int gy = y0 - 1 + k;
        vbuf[k] = make_float4(0.f, 0.f, 0.f, 0.f);
        ebuf[k] = 0.f;
        if (INTERIOR || (unsigned)gy < (unsigned)Hv) {
            vbuf[k] = ((const float4*)(px + gy * Wv))[tid];
            if (ev) ebuf[k] = px[gy * Wv + eoff];
        }
    }

#pragma unroll
    for (int i = 0; i < RSTRIP + 2; i++) {
        const int gy = y0 - 1 + i;
        float4 v = vbuf[i & 1];
        float eraw = ebuf[i & 1];

        // Prefetch row gy+2 into the slot just freed
        if (i < RSTRIP) {
            const int gy2 = gy + 2;
            float4 vp = make_float4(0.f, 0.f, 0.f, 0.f);
            float ep = 0.f;
            if (INTERIOR || gy2 < Hv) {
                vp = ((const float4*)(px + gy2 * Wv))[tid];
                if (ev) ep = px[gy2 * Wv + eoff];
            }
            vbuf[i & 1] = vp;
            ebuf[i & 1] = ep;
        }

        // Transform: sat(x^g * (w*ct) + beta)  -> FFMA.SAT
        float f0 = __saturatef(fmaf(fast_pow(v.x, g), wct, beta));
        float f1 = __saturatef(fmaf(fast_pow(v.y, g), wct, beta));
        float f2 = __saturatef(fmaf(fast_pow(v.z, g), wct, beta));
        float f3 = __saturatef(fmaf(fast_pow(v.w, g), wct, beta));
        float e  = __saturatef(fmaf(fast_pow(eraw, g), wct, beta));
        if (!INTERIOR) {
            const bool vval = (unsigned)gy < (unsigned)Hv;
            if (!vval) { f0 = f1 = f2 = f3 = 0.f; }
            if (!(vval && ev)) e = 0.f;
        } else {
            if (!ev) e = 0.f;
        }

        // Horizontal neighbors via shuffle (warp edges use e)
        float fl = __shfl_up_sync(0xFFFFFFFFu, f3, 1);
        if (lane == 0) fl = e;
        float fr = __shfl_down_sync(0xFFFFFFFFu, f0, 1);
        if (lane == 31) fr = e;

        float rs2_0 = fl + f0 + f1;
        float rs2_1 = f0 + f1 + f2;
        float rs2_2 = f1 + f2 + f3;
        float rs2_3 = f2 + f3 + fr;

        // Emit output row gy-1: out = sat(s*(9c - s9) + c)
        if (i >= 2) {
            float4 o4;
            float s9, c;

            c = ctr[0]; s9 = rs0[0] + rs1[0] + rs2_0;
            o4.x = __saturatef(fmaf(s, fmaf(9.f, c, -s9), c));

            c = ctr[1]; s9 = rs0[1] + rs1[1] + rs2_1;
            o4.y = __saturatef(fmaf(s, fmaf(9.f, c, -s9), c));

            c = ctr[2]; s9 = rs0[2] + rs1[2] + rs2_2;
            o4.z = __saturatef(fmaf(s, fmaf(9.f, c, -s9), c));

            c = ctr[3]; s9 = rs0[3] + rs1[3] + rs2_3;
            o4.w = __saturatef(fmaf(s, fmaf(9.f, c, -s9), c));

            ((float4*)(po + (gy - 1) * Wv))[tid] = o4;
        }

        // Rotate pipeline registers (renamed away by the full unroll)
        rs0[0] = rs1[0]; rs0[1] = rs1[1]; rs0[2] = rs1[2]; rs0[3] = rs1[3];
        rs1[0] = rs2_0;  rs1[1] = rs2_1;  rs1[2] = rs2_2;  rs1[3] = rs2_3;
        ctr[0] = f0; ctr[1] = f1; ctr[2] = f2; ctr[3] = f3;
    }
}

__global__ void __launch_bounds__(128) k2_main(const float* __restrict__ x,
                                               const float* __restrict__ gamma,
                                               const float* __restrict__ wb,
                                               const float* __restrict__ contrast,
                                               const float* __restrict__ sharpen,
                                               float* __restrict__ out) {
    const int plane = blockIdx.y;            // b*3 + c
    const int b = plane / Cv;
    const float g  = __ldg(&gamma[b]);
    const float w  = __ldg(&wb[plane]);      // wb[b][c] flattens to wb[plane]
    const float ct = __ldg(&contrast[b]);
    const float s  = __ldg(&sharpen[b]);
    const float wct = w * ct;                // fold wb into contrast scale

    __shared__ float s_beta;
    const int tid  = threadIdx.x;
    const int lane = tid & 31;

    // Fold per-plane partials: warp 0, one load + shfl reduce.
    if (tid < 32) {
        float p = d_partial[plane * K1_BLOCKS_PER_PLANE + tid];
#pragma unroll
        for (int o = 16; o; o >>= 1) p += __shfl_xor_sync(0xFFFFFFFFu, p, o);
        if (tid == 0) {
            float mean = p * w * (1.0f / (float)PLANE);
            s_beta = mean - mean * ct;       // mean*(1-contrast)
        }
    }
    __syncthreads();
    const float beta = s_beta;

    const float* __restrict__ px = x + (size_t)plane * PLANE;
    float* __restrict__ po = out + (size_t)plane * PLANE;
    const int y0 = blockIdx.x * RSTRIP;

    if (y0 >= RSTRIP && y0 + RSTRIP < Hv)
        k2_body<true>(px, po, y0, tid, lane, g, wct, beta, s);
    else
        k2_body<false>(px, po, y0, tid, lane, g, wct, beta, s);
}

extern "C" void kernel_launch(void* const* d_in, const int* in_sizes, int n_in,
                              void* d_out, int out_size) {
    const float* x        = (const float*)d_in[0];
    const float* gamma    = (const float*)d_in[1];
    const float* wb       = (const float*)d_in[2];
    const float* contrast = (const float*)d_in[3];
    const float* sharpen  = (const float*)d_in[4];
    float* out = (float*)d_out;

    dim3 g1(K1_BLOCKS_PER_PLANE, NPLANES);
    k1_pow_sum<<<g1, 256>>>(x, gamma);
    dim3 g2(Hv / RSTRIP, NPLANES);           // 32 strips x 96 planes = 3072 blocks
    k2_main<<<g2, 128>>>(x, gamma, wb, contrast, sharpen, out);
}

// round 7
// speedup vs baseline: 1.2780x; 1.1498x over previous
#include <cuda_runtime.h>
#include <cuda_bf16.h>

// Problem constants: B=32, C=3, H=W=512
#define Bv 32
#define Cv 3
#define Hv 512
#define Wv 512
#define PLANE (Hv*Wv)            // 262144
#define NPLANES (Bv*Cv)          // 96
#define K1_BLOCKS_PER_PLANE 32
#define RSTRIP 16                // output rows per K2 block

// Deterministic partial sums (no atomics): one slot per (plane, block)
__device__ float d_partial[NPLANES * K1_BLOCKS_PER_PLANE];

__device__ __forceinline__ float fast_pow(float x, float g) {
    return __powf(x, g);         // MUFU.LG2 + FMUL + MUFU.EX2 ; 0^g -> 0 correct
}

// ---------------- Kernel 1: per-plane sum of x^gamma ----------------
// Default-cached reads: these populate L2 with x for K2's re-read.
__global__ void __launch_bounds__(256) k1_pow_sum(const float* __restrict__ x,
                                                 const float* __restrict__ gamma) {
    const int plane = blockIdx.y;            // b*3 + c
    const int b = plane / Cv;
    const float g = __ldg(&gamma[b]);
    const float4* px = (const float4*)(x + (size_t)plane * PLANE);

    float s0 = 0.f, s1 = 0.f, s2 = 0.f, s3 = 0.f;
    int base = blockIdx.x * 2048 + threadIdx.x;   // 2048 float4 per block
#pragma unroll
    for (int k = 0; k < 8; k++) {
        float4 v = px[base + k * 256];
        s0 += fast_pow(v.x, g);
        s1 += fast_pow(v.y, g);
        s2 += fast_pow(v.z, g);
        s3 += fast_pow(v.w, g);
    }
    float s = (s0 + s1) + (s2 + s3);
#pragma unroll
    for (int o = 16; o; o >>= 1) s += __shfl_xor_sync(0xFFFFFFFFu, s, o);

    __shared__ float ws[8];
    int lane = threadIdx.x & 31, w = threadIdx.x >> 5;
    if (lane == 0) ws[w] = s;
    __syncthreads();
    if (w == 0) {
        s = (lane < 8) ? ws[lane] : 0.f;
#pragma unroll
        for (int o = 4; o; o >>= 1) s += __shfl_xor_sync(0xFFFFFFFFu, s, o);
        if (lane == 0) d_partial[plane * K1_BLOCKS_PER_PLANE + blockIdx.x] = s;
    }
}

// ---------------- Kernel 2 body: rolling register pipeline ----------------
// Thread t owns output columns 4t..4t+3 of a full 512-wide row. Walks
// RSTRIP+2 input rows with depth-2 prefetch; horizontal halo via shuffles +
// 2 predicated scalar LDG at warp edges. x reads are last-use (__ldlu),
// out stores are evict-first streaming (__stcs) so they don't evict x from L2.
template <bool INTERIOR>
__device__ __forceinline__ void k2_body(const float* __restrict__ px,
                                        float* __restrict__ po,
                                        int y0, int tid, int lane,
                                        float g, float wct, float beta, float s) {
    const int cbase = (tid >> 5) * 128;      // warp's first column
    const bool evL = (lane == 0)  && (cbase > 0);
    const bool evR = (lane == 31) && (cbase + 128 < Wv);
    const int eoff = evL ? (cbase - 1) : (cbase + 128);
    const bool ev  = evL || evR;

    float rs0[4] = {0.f, 0.f, 0.f, 0.f};
    float rs1[4] = {0.f, 0.f, 0.f, 0.f};
    float ctr[4] = {0.f, 0.f, 0.f, 0.f};

    float4 vbuf[2];
    float  ebuf[2];

    // Prologue: prefetch rows y0-1 and y0
#pragma unroll
    for (int k = 0; k < 2; k++) {
        int gy = y0 - 1 + k;
        vbuf[k] = make_float4(0.f, 0.f, 0.f, 0.f);
        ebuf[k] = 0.f;
        if (INTERIOR || (unsigned)gy < (unsigned)Hv) {
            vbuf[k] = __ldlu(((const float4*)(px + gy * Wv)) + tid);
            if (ev) ebuf[k] = __ldlu(px + gy * Wv + eoff);
        }
    }

#pragma unroll
    for (int i = 0; i < RSTRIP + 2; i++) {
        const int gy = y0 - 1 + i;
        float4 v = vbuf[i & 1];
        float eraw = ebuf[i & 1];

        // Prefetch row gy+2 into the slot just freed
        if (i < RSTRIP) {
            const int gy2 = gy + 2;
            float4 vp = make_float4(0.f, 0.f, 0.f, 0.f);
            float ep = 0.f;
            if (INTERIOR || gy2 < Hv) {
                vp = __ldlu(((const float4*)(px + gy2 * Wv)) + tid);
                if (ev) ep = __ldlu(px + gy2 * Wv + eoff);
            }
            vbuf[i & 1] = vp;
            ebuf[i & 1] = ep;
        }

        // Transform: sat(x^g * (w*ct) + beta)  -> FFMA.SAT
        float f0 = __saturatef(fmaf(fast_pow(v.x, g), wct, beta));
        float f1 = __saturatef(fmaf(fast_pow(v.y, g), wct, beta));
        float f2 = __saturatef(fmaf(fast_pow(v.z, g), wct, beta));
        float f3 = __saturatef(fmaf(fast_pow(v.w, g), wct, beta));
        float e  = __saturatef(fmaf(fast_pow(eraw, g), wct, beta));
        if (!INTERIOR) {
            const bool vval = (unsigned)gy < (unsigned)Hv;
            if (!vval) { f0 = f1 = f2 = f3 = 0.f; }
            if (!(vval && ev)) e = 0.f;
        } else {
            if (!ev) e = 0.f;
        }

        // Horizontal neighbors via shuffle (warp edges use e)
        float fl = __shfl_up_sync(0xFFFFFFFFu, f3, 1);
        if (lane == 0) fl = e;
        float fr = __shfl_down_sync(0xFFFFFFFFu, f0, 1);
        if (lane == 31) fr = e;

        float rs2_0 = fl + f0 + f1;
        float rs2_1 = f0 + f1 + f2;
        float rs2_2 = f1 + f2 + f3;
        float rs2_3 = f2 + f3 + fr;

        // Emit output row gy-1: out = sat(s*(9c - s9) + c)
        if (i >= 2) {
            float4 o4;
            float s9, c;

            c = ctr[0]; s9 = rs0[0] + rs1[0] + rs2_0;
            o4.x = __saturatef(fmaf(s, fmaf(9.f, c, -s9), c));

            c = ctr[1]; s9 = rs0[1] + rs1[1] + rs2_1;
            o4.y = __saturatef(fmaf(s, fmaf(9.f, c, -s9), c));

            c = ctr[2]; s9 = rs0[2] + rs1[2] + rs2_2;
            o4.z = __saturatef(fmaf(s, fmaf(9.f, c, -s9), c));

            c = ctr[3]; s9 = rs0[3] + rs1[3] + rs2_3;
            o4.w = __saturatef(fmaf(s, fmaf(9.f, c, -s9), c));

            __stcs(((float4*)(po + (gy - 1) * Wv)) + tid, o4);
        }

        // Rotate pipeline registers (renamed away by the full unroll)
        rs0[0] = rs1[0]; rs0[1] = rs1[1]; rs0[2] = rs1[2]; rs0[3] = rs1[3];
        rs1[0] = rs2_0;  rs1[1] = rs2_1;  rs1[2] = rs2_2;  rs1[3] = rs2_3;
        ctr[0] = f0; ctr[1] = f1; ctr[2] = f2; ctr[3] = f3;
    }
}

__global__ void __launch_bounds__(128) k2_main(const float* __restrict__ x,
                                               const float* __restrict__ gamma,
                                               const float* __restrict__ wb,
                                               const float* __restrict__ contrast,
                                               const float* __restrict__ sharpen,
                                               float* __restrict__ out) {
    const int plane = blockIdx.y;            // b*3 + c
    const int b = plane / Cv;
    const float g  = __ldg(&gamma[b]);
    const float w  = __ldg(&wb[plane]);      // wb[b][c] flattens to wb[plane]
    const float ct = __ldg(&contrast[b]);
    const float s  = __ldg(&sharpen[b]);
    const float wct = w * ct;                // fold wb into contrast scale

    __shared__ float s_beta;
    const int tid  = threadIdx.x;
    const int lane = tid & 31;

    // Fold per-plane partials: warp 0, one load + shfl reduce.
    if (tid < 32) {
        float p = d_partial[plane * K1_BLOCKS_PER_PLANE + tid];
#pragma unroll
        for (int o = 16; o; o >>= 1) p += __shfl_xor_sync(0xFFFFFFFFu, p, o);
        if (tid == 0) {
            float mean = p * w * (1.0f / (float)PLANE);
            s_beta = mean - mean * ct;       // mean*(1-contrast)
        }
    }
    __syncthreads();
    const float beta = s_beta;

    const float* __restrict__ px = x + (size_t)plane * PLANE;
    float* __restrict__ po = out + (size_t)plane * PLANE;
    const int y0 = blockIdx.x * RSTRIP;

    if (y0 >= RSTRIP && y0 + RSTRIP < Hv)
        k2_body<true>(px, po, y0, tid, lane, g, wct, beta, s);
    else
        k2_body<false>(px, po, y0, tid, lane, g, wct, beta, s);
}

extern "C" void kernel_launch(void* const* d_in, const int* in_sizes, int n_in,
                              void* d_out, int out_size) {
    const float* x        = (const float*)d_in[0];
    const float* gamma    = (const float*)d_in[1];
    const float* wb       = (const float*)d_in[2];
    const float* contrast = (const float*)d_in[3];
    const float* sharpen  = (const float*)d_in[4];
    float* out = (float*)d_out;

    dim3 g1(K1_BLOCKS_PER_PLANE, NPLANES);
    k1_pow_sum<<<g1, 256>>>(x, gamma);
    dim3 g2(Hv / RSTRIP, NPLANES);           // 32 strips x 96 planes = 3072 blocks
    k2_main<<<g2, 128>>>(x, gamma, wb, contrast, sharpen, out);
}